// round 4
// baseline (speedup 1.0000x reference)
#include <cuda_runtime.h>

#define POS_DIM 15
#define N_LAYERS 32
#define H 16
#define IN_DIM (4 + 4 * 2 * POS_DIM)   // 124
#define NEG_SLOPE 0.2f

#define THREADS 256

// Shared weight staging sizes (floats)
#define W1_N (IN_DIM * H)        // 1984
#define WS_N (N_LAYERS * H * H)  // 8192
#define BS_N (N_LAYERS * H)      // 512

__global__ __launch_bounds__(THREADS, 4)
void fractal_mlp_kernel(const float* __restrict__ z,
                        const float* __restrict__ c,
                        const float* __restrict__ W1,
                        const float* __restrict__ b1,
                        const float* __restrict__ Ws,
                        const float* __restrict__ bs,
                        const float* __restrict__ Wf,
                        const float* __restrict__ bf,
                        float* __restrict__ out,
                        int B)
{
    __shared__ float sW1[W1_N];
    __shared__ float sWs[WS_N];
    __shared__ float sBs[BS_N];
    __shared__ float sB1[H];
    __shared__ float sWf[H];
    __shared__ float sBf;

    const int tid = threadIdx.x;

    // Cooperative stage of all weights into SMEM (L2-resident after first wave)
    for (int i = tid; i < W1_N; i += THREADS) sW1[i] = W1[i];
    for (int i = tid; i < WS_N; i += THREADS) sWs[i] = Ws[i];
    for (int i = tid; i < BS_N; i += THREADS) sBs[i] = bs[i];
    if (tid < H) { sB1[tid] = b1[tid]; sWf[tid] = Wf[tid]; }
    if (tid == 0) sBf = bf[0];
    __syncthreads();

    const int row = blockIdx.x * THREADS + tid;
    if (row >= B) return;

    // x = concat([z, c]) : (4,)
    float x0 = z[row * 2 + 0];
    float x1 = z[row * 2 + 1];
    float x2 = c[row * 2 + 0];
    float x3 = c[row * 2 + 1];
    float xv[4] = {x0, x1, x2, x3};

    // ---- First layer: acc = b1 + encoded(x) @ W1, computed feature-by-feature ----
    float acc[H];
#pragma unroll
    for (int j = 0; j < H; j++) acc[j] = sB1[j];

    const float4* w1v = reinterpret_cast<const float4*>(sW1);

    // helper: acc += v * W1[feat, :]
#define ACCUM_FEAT(feat, v)                                   \
    {                                                         \
        const float vv = (v);                                 \
        const float4* r = w1v + (feat) * (H / 4);             \
        _Pragma("unroll")                                     \
        for (int q = 0; q < H / 4; q++) {                     \
            float4 w = r[q];                                  \
            acc[4 * q + 0] = fmaf(vv, w.x, acc[4 * q + 0]);   \
            acc[4 * q + 1] = fmaf(vv, w.y, acc[4 * q + 1]);   \
            acc[4 * q + 2] = fmaf(vv, w.z, acc[4 * q + 2]);   \
            acc[4 * q + 3] = fmaf(vv, w.w, acc[4 * q + 3]);   \
        }                                                     \
    }

#pragma unroll
    for (int d = 0; d < 4; d++) ACCUM_FEAT(d, xv[d]);

    // positional encoding features: feat = 4 + f*8 + t*4 + d  (t=0:sin, t=1:cos)
#pragma unroll 1
    for (int f = 0; f < POS_DIM; f++) {
        const float scale = (float)(1 << f);   // 2^f, exact
#pragma unroll
        for (int d = 0; d < 4; d++) {
            float s, cn;
            sincosf(xv[d] * scale, &s, &cn);    // accurate path; |arg| < 105615
            ACCUM_FEAT(4 + f * 8 + d,     s);
            ACCUM_FEAT(4 + f * 8 + 4 + d, cn);
        }
    }

    float h[H];
#pragma unroll
    for (int j = 0; j < H; j++)
        h[j] = fmaxf(acc[j], NEG_SLOPE * acc[j]);   // leaky_relu

    // ---- 32 residual layers: h += leaky(h @ W + b) ----
#pragma unroll 1
    for (int L = 0; L < N_LAYERS; L++) {
        const float4* w = reinterpret_cast<const float4*>(sWs + L * H * H);
        const float*  bb = sBs + L * H;
        float a[H];
#pragma unroll
        for (int j = 0; j < H; j++) a[j] = bb[j];
#pragma unroll
        for (int k = 0; k < H; k++) {
            const float hk = h[k];
#pragma unroll
            for (int q = 0; q < H / 4; q++) {
                float4 wv = w[k * (H / 4) + q];
                a[4 * q + 0] = fmaf(hk, wv.x, a[4 * q + 0]);
                a[4 * q + 1] = fmaf(hk, wv.y, a[4 * q + 1]);
                a[4 * q + 2] = fmaf(hk, wv.z, a[4 * q + 2]);
                a[4 * q + 3] = fmaf(hk, wv.w, a[4 * q + 3]);
            }
        }
#pragma unroll
        for (int j = 0; j < H; j++)
            h[j] += fmaxf(a[j], NEG_SLOPE * a[j]);
    }

    // ---- Final: out = h @ Wf + bf ----
    float o = sBf;
#pragma unroll
    for (int j = 0; j < H; j++) o = fmaf(h[j], sWf[j], o);
    out[row] = o;
}

extern "C" void kernel_launch(void* const* d_in, const int* in_sizes, int n_in,
                              void* d_out, int out_size)
{
    const float* z  = (const float*)d_in[0];
    const float* c  = (const float*)d_in[1];
    const float* W1 = (const float*)d_in[2];
    const float* b1 = (const float*)d_in[3];
    const float* Ws = (const float*)d_in[4];
    const float* bs = (const float*)d_in[5];
    const float* Wf = (const float*)d_in[6];
    const float* bf = (const float*)d_in[7];

    const int B = in_sizes[0] / 2;   // z is (B, 2)
    const int blocks = (B + THREADS - 1) / THREADS;

    fractal_mlp_kernel<<<blocks, THREADS>>>(z, c, W1, b1, Ws, bs, Wf, bf,
                                            (float*)d_out, B);
}

// round 5
// speedup vs baseline: 1.5985x; 1.5985x over previous
#include <cuda_runtime.h>

typedef unsigned long long u64;

#define POS_DIM 15
#define N_LAYERS 32
#define H 16
#define IN_DIM (4 + 4 * 2 * POS_DIM)   // 124
#define THREADS 256
#define ROWS 2                          // rows per thread

#define W1_N (IN_DIM * H)        // 1984
#define WS_N (N_LAYERS * H * H)  // 8192
#define BS_N (N_LAYERS * H)      // 512

// ---- packed f32x2 helpers (Blackwell packed fp32 math) ----
__device__ __forceinline__ u64 pack2(float lo, float hi) {
    u64 r; asm("mov.b64 %0, {%1, %2};" : "=l"(r) : "f"(lo), "f"(hi)); return r;
}
__device__ __forceinline__ void unpack2(u64 v, float& lo, float& hi) {
    asm("mov.b64 {%0, %1}, %2;" : "=f"(lo), "=f"(hi) : "l"(v));
}
__device__ __forceinline__ u64 fma2(u64 a, u64 b, u64 c) {
    u64 d; asm("fma.rn.f32x2 %0, %1, %2, %3;" : "=l"(d) : "l"(a), "l"(b), "l"(c)); return d;
}
__device__ __forceinline__ u64 mul2(u64 a, u64 b) {
    u64 d; asm("mul.rn.f32x2 %0, %1, %2;" : "=l"(d) : "l"(a), "l"(b)); return d;
}
__device__ __forceinline__ u64 abs2(u64 a) { return a & 0x7fffffff7fffffffULL; }

// 0.6f = 0x3F19999A, 0.4f = 0x3ECCCCCD  (leaky(x) = 0.6x + 0.4|x| for slope 0.2)
#define C06 0x3F19999A3F19999AULL
#define C04 0x3ECCCCCD3ECCCCCDULL

__global__ __launch_bounds__(THREADS, 2)
void fractal_mlp_kernel(const float* __restrict__ z,
                        const float* __restrict__ c,
                        const float* __restrict__ W1,
                        const float* __restrict__ b1,
                        const float* __restrict__ Ws,
                        const float* __restrict__ bs,
                        const float* __restrict__ Wf,
                        const float* __restrict__ bf,
                        float* __restrict__ out,
                        int B)
{
    __shared__ __align__(16) float sW1[W1_N];
    __shared__ __align__(16) float sWs[WS_N];
    __shared__ __align__(16) float sBs[BS_N];
    __shared__ __align__(16) float sB1[H];
    __shared__ __align__(16) float sWf[H];
    __shared__ float sBf;

    const int tid = threadIdx.x;
    for (int i = tid; i < W1_N; i += THREADS) sW1[i] = W1[i];
    for (int i = tid; i < WS_N; i += THREADS) sWs[i] = Ws[i];
    for (int i = tid; i < BS_N; i += THREADS) sBs[i] = bs[i];
    if (tid < H) { sB1[tid] = b1[tid]; sWf[tid] = Wf[tid]; }
    if (tid == 0) sBf = bf[0];
    __syncthreads();

    const int base = blockIdx.x * (THREADS * ROWS) + tid;
    const int rowA = base;
    const int rowB = base + THREADS;
    // B = 524288 is divisible by 512, but clamp defensively
    const int rA = rowA < B ? rowA : B - 1;
    const int rB = rowB < B ? rowB : B - 1;

    const float2* z2 = reinterpret_cast<const float2*>(z);
    const float2* c2 = reinterpret_cast<const float2*>(c);
    float2 zA = z2[rA], cA = c2[rA];
    float2 zB = z2[rB], cB = c2[rB];
    float xA[4] = {zA.x, zA.y, cA.x, cA.y};
    float xB[4] = {zB.x, zB.y, cB.x, cB.y};

    // ---- First layer: acc = b1 + encoded(x) @ W1 (packed pairs over output j) ----
    u64 accA[8], accB[8];
    {
        const ulonglong2* b1v = reinterpret_cast<const ulonglong2*>(sB1);
#pragma unroll
        for (int q = 0; q < 4; q++) {
            ulonglong2 t = b1v[q];
            accA[2 * q] = t.x; accA[2 * q + 1] = t.y;
            accB[2 * q] = t.x; accB[2 * q + 1] = t.y;
        }
    }

    const ulonglong2* w1v = reinterpret_cast<const ulonglong2*>(sW1);

#define ACC2(feat, vA, vB)                                            \
    {                                                                 \
        const u64 pA = pack2((vA), (vA));                             \
        const u64 pB = pack2((vB), (vB));                             \
        const ulonglong2* r = w1v + (feat) * 4;                       \
        _Pragma("unroll")                                             \
        for (int q = 0; q < 4; q++) {                                 \
            ulonglong2 wv = r[q];                                     \
            accA[2 * q]     = fma2(pA, wv.x, accA[2 * q]);            \
            accA[2 * q + 1] = fma2(pA, wv.y, accA[2 * q + 1]);        \
            accB[2 * q]     = fma2(pB, wv.x, accB[2 * q]);            \
            accB[2 * q + 1] = fma2(pB, wv.y, accB[2 * q + 1]);        \
        }                                                             \
    }

#pragma unroll
    for (int d = 0; d < 4; d++) ACC2(d, xA[d], xB[d]);

    // positional-encoding features via anchored double-angle recurrence.
    // anchors f=0,5,10 use accurate sincosf; f+1..f+4 derived by doubling
    // (s' = 2sc, c' = c^2 - s^2). Amplification <= 16 => error ~2e-6.
#pragma unroll 1
    for (int d = 0; d < 4; d++) {
        const float aAv = xA[d];
        const float aBv = xB[d];
#pragma unroll
        for (int an = 0; an < 3; an++) {
            const float sc = (an == 0) ? 1.0f : ((an == 1) ? 32.0f : 1024.0f);
            float sA, cAv, sB, cBv;
            sincosf(aAv * sc, &sA, &cAv);
            sincosf(aBv * sc, &sB, &cBv);
#pragma unroll
            for (int g = 0; g < 5; g++) {
                const int f = an * 5 + g;
                ACC2(4 + f * 8 + d, sA, sB);       // sin feature
                ACC2(8 + f * 8 + d, cAv, cBv);     // cos feature
                if (g < 4) {
                    float tA = sA * cAv;
                    float nA = fmaf(cAv, cAv, -(sA * sA));
                    sA = tA + tA; cAv = nA;
                    float tB = sB * cBv;
                    float nB = fmaf(cBv, cBv, -(sB * sB));
                    sB = tB + tB; cBv = nB;
                }
            }
        }
    }

    // leaky into h (scalar form for broadcast packing in the layer loop)
    float hA[H], hB[H];
#pragma unroll
    for (int p = 0; p < 8; p++) {
        u64 tA = accA[p];
        u64 rAp = fma2(abs2(tA), C04, mul2(tA, C06));
        unpack2(rAp, hA[2 * p], hA[2 * p + 1]);
        u64 tB = accB[p];
        u64 rBp = fma2(abs2(tB), C04, mul2(tB, C06));
        unpack2(rBp, hB[2 * p], hB[2 * p + 1]);
    }

    // ---- 32 residual layers: h += leaky(h @ W + b) ----
#pragma unroll 1
    for (int L = 0; L < N_LAYERS; L++) {
        const ulonglong2* w = reinterpret_cast<const ulonglong2*>(sWs + L * H * H);
        const ulonglong2* bb = reinterpret_cast<const ulonglong2*>(sBs + L * H);
        u64 aA[8], aB[8];
#pragma unroll
        for (int q = 0; q < 4; q++) {
            ulonglong2 t = bb[q];
            aA[2 * q] = t.x; aA[2 * q + 1] = t.y;
            aB[2 * q] = t.x; aB[2 * q + 1] = t.y;
        }
#pragma unroll
        for (int k = 0; k < H; k++) {
            const u64 vA = pack2(hA[k], hA[k]);
            const u64 vB = pack2(hB[k], hB[k]);
#pragma unroll
            for (int q = 0; q < 4; q++) {
                ulonglong2 wv = w[k * 4 + q];
                aA[2 * q]     = fma2(vA, wv.x, aA[2 * q]);
                aA[2 * q + 1] = fma2(vA, wv.y, aA[2 * q + 1]);
                aB[2 * q]     = fma2(vB, wv.x, aB[2 * q]);
                aB[2 * q + 1] = fma2(vB, wv.y, aB[2 * q + 1]);
            }
        }
#pragma unroll
        for (int p = 0; p < 8; p++) {
            u64 tA = aA[p];
            u64 rAp = fma2(abs2(tA), C04, mul2(tA, C06));
            float r0, r1; unpack2(rAp, r0, r1);
            hA[2 * p] += r0; hA[2 * p + 1] += r1;
            u64 tB = aB[p];
            u64 rBp = fma2(abs2(tB), C04, mul2(tB, C06));
            float s0, s1; unpack2(rBp, s0, s1);
            hB[2 * p] += s0; hB[2 * p + 1] += s1;
        }
    }

    // ---- Final: out = h @ Wf + bf ----
    float oA = sBf, oB = sBf;
#pragma unroll
    for (int j = 0; j < H; j++) {
        oA = fmaf(hA[j], sWf[j], oA);
        oB = fmaf(hB[j], sWf[j], oB);
    }
    if (rowA < B) out[rowA] = oA;
    if (rowB < B) out[rowB] = oB;
}

extern "C" void kernel_launch(void* const* d_in, const int* in_sizes, int n_in,
                              void* d_out, int out_size)
{
    const float* z  = (const float*)d_in[0];
    const float* c  = (const float*)d_in[1];
    const float* W1 = (const float*)d_in[2];
    const float* b1 = (const float*)d_in[3];
    const float* Ws = (const float*)d_in[4];
    const float* bs = (const float*)d_in[5];
    const float* Wf = (const float*)d_in[6];
    const float* bf = (const float*)d_in[7];

    const int B = in_sizes[0] / 2;   // z is (B, 2)
    const int rows_per_block = THREADS * ROWS;
    const int blocks = (B + rows_per_block - 1) / rows_per_block;

    fractal_mlp_kernel<<<blocks, THREADS>>>(z, c, W1, b1, Ws, bs, Wf, bf,
                                            (float*)d_out, B);
}

// round 8
// speedup vs baseline: 1.6736x; 1.0470x over previous
#include <cuda_runtime.h>

typedef unsigned long long u64;

#define POS_DIM 15
#define N_LAYERS 32
#define H 16
#define IN_DIM (4 + 4 * 2 * POS_DIM)   // 124
#define THREADS 256
#define ROWS 2                          // rows per thread

#define W1_N (IN_DIM * H)        // 1984
#define WS_N (N_LAYERS * H * H)  // 8192
#define BS_N (N_LAYERS * H)      // 512

// ---- packed f32x2 helpers ----
__device__ __forceinline__ u64 pack2(float lo, float hi) {
    u64 r; asm("mov.b64 %0, {%1, %2};" : "=l"(r) : "f"(lo), "f"(hi)); return r;
}
__device__ __forceinline__ void unpack2(u64 v, float& lo, float& hi) {
    asm("mov.b64 {%0, %1}, %2;" : "=f"(lo), "=f"(hi) : "l"(v));
}
__device__ __forceinline__ u64 fma2(u64 a, u64 b, u64 c) {
    u64 d; asm("fma.rn.f32x2 %0, %1, %2, %3;" : "=l"(d) : "l"(a), "l"(b), "l"(c)); return d;
}
__device__ __forceinline__ u64 mul2(u64 a, u64 b) {
    u64 d; asm("mul.rn.f32x2 %0, %1, %2;" : "=l"(d) : "l"(a), "l"(b)); return d;
}
__device__ __forceinline__ u64 abs2(u64 a) { return a & 0x7fffffff7fffffffULL; }

// leaky(x) = 0.6x + 0.4|x|  (exact for slope 0.2)
#define C06 0x3F19999A3F19999AULL
#define C04 0x3ECCCCCD3ECCCCCDULL

// h_new = h_old + leaky(t)  in 2 fma-pipe ops (LOP3 rides the alu pipe)
__device__ __forceinline__ u64 resleaky2(u64 t, u64 h_old) {
    return fma2(abs2(t), C04, fma2(t, C06, h_old));
}
// leaky(t) alone (first layer): mul2 + fma2
__device__ __forceinline__ u64 leaky2(u64 t) {
    return fma2(abs2(t), C04, mul2(t, C06));
}

__global__ __launch_bounds__(THREADS, 2)
void fractal_mlp_kernel(const float* __restrict__ z,
                        const float* __restrict__ c,
                        const float* __restrict__ W1,
                        const float* __restrict__ b1,
                        const float* __restrict__ Ws,
                        const float* __restrict__ bs,
                        const float* __restrict__ Wf,
                        const float* __restrict__ bf,
                        float* __restrict__ out,
                        int B)
{
    __shared__ __align__(16) float sW1[W1_N];
    __shared__ __align__(16) float sWs[WS_N];
    __shared__ __align__(16) float sBs[BS_N];
    __shared__ __align__(16) float sB1[H];
    __shared__ __align__(16) float sWf[H];
    __shared__ float sBf;

    const int tid = threadIdx.x;
    {   // vectorized staging
        const float4* g; float4* s;
        g = (const float4*)W1; s = (float4*)sW1;
        for (int i = tid; i < W1_N / 4; i += THREADS) s[i] = g[i];
        g = (const float4*)Ws; s = (float4*)sWs;
        for (int i = tid; i < WS_N / 4; i += THREADS) s[i] = g[i];
        g = (const float4*)bs; s = (float4*)sBs;
        for (int i = tid; i < BS_N / 4; i += THREADS) s[i] = g[i];
        if (tid < H) { sB1[tid] = b1[tid]; sWf[tid] = Wf[tid]; }
        if (tid == 0) sBf = bf[0];
    }
    __syncthreads();

    const int base = blockIdx.x * (THREADS * ROWS) + tid;
    const int rowA = base;
    const int rowB = base + THREADS;
    const int rA = rowA < B ? rowA : B - 1;
    const int rB = rowB < B ? rowB : B - 1;

    const float2* z2 = reinterpret_cast<const float2*>(z);
    const float2* c2 = reinterpret_cast<const float2*>(c);
    float2 zA = z2[rA], cA = c2[rA];
    float2 zB = z2[rB], cB = c2[rB];
    float xA[4] = {zA.x, zA.y, cA.x, cA.y};
    float xB[4] = {zB.x, zB.y, cB.x, cB.y};

    // ---- First layer: acc = b1 + encoded(x) @ W1 (packed over output j pairs) ----
    u64 accA[8], accB[8];
    {
        const ulonglong2* b1v = reinterpret_cast<const ulonglong2*>(sB1);
#pragma unroll
        for (int q = 0; q < 4; q++) {
            ulonglong2 t = b1v[q];
            accA[2 * q] = t.x; accA[2 * q + 1] = t.y;
            accB[2 * q] = t.x; accB[2 * q + 1] = t.y;
        }
    }

    const ulonglong2* w1v = reinterpret_cast<const ulonglong2*>(sW1);

#define ACC2(feat, vA, vB)                                            \
    {                                                                 \
        const u64 pA = pack2((vA), (vA));                             \
        const u64 pB = pack2((vB), (vB));                             \
        const ulonglong2* r = w1v + (feat) * 4;                       \
        _Pragma("unroll")                                             \
        for (int q = 0; q < 4; q++) {                                 \
            ulonglong2 wv = r[q];                                     \
            accA[2 * q]     = fma2(pA, wv.x, accA[2 * q]);            \
            accA[2 * q + 1] = fma2(pA, wv.y, accA[2 * q + 1]);        \
            accB[2 * q]     = fma2(pB, wv.x, accB[2 * q]);            \
            accB[2 * q + 1] = fma2(pB, wv.y, accB[2 * q + 1]);        \
        }                                                             \
    }

#pragma unroll
    for (int d = 0; d < 4; d++) ACC2(d, xA[d], xB[d]);

    // positional encoding: anchored double-angle (anchors f=0,5,10; 4 doublings each)
#pragma unroll 1
    for (int d = 0; d < 4; d++) {
        const float aAv = xA[d];
        const float aBv = xB[d];
#pragma unroll
        for (int an = 0; an < 3; an++) {
            const float sc = (an == 0) ? 1.0f : ((an == 1) ? 32.0f : 1024.0f);
            float sA, cAv, sB, cBv;
            sincosf(aAv * sc, &sA, &cAv);
            sincosf(aBv * sc, &sB, &cBv);
#pragma unroll
            for (int g = 0; g < 5; g++) {
                const int f = an * 5 + g;
                ACC2(4 + f * 8 + d, sA, sB);       // sin feature
                ACC2(8 + f * 8 + d, cAv, cBv);     // cos feature
                if (g < 4) {
                    float tA = sA * cAv;
                    float nA = fmaf(cAv, cAv, -(sA * sA));
                    sA = tA + tA; cAv = nA;
                    float tB = sB * cBv;
                    float nB = fmaf(cBv, cBv, -(sB * sB));
                    sB = tB + tB; cBv = nB;
                }
            }
        }
    }

    // first-layer leaky -> scalar h (scalars feed the per-k splats)
    float hA[H], hB[H];
#pragma unroll
    for (int p = 0; p < 8; p++) {
        unpack2(leaky2(accA[p]), hA[2 * p], hA[2 * p + 1]);
        unpack2(leaky2(accB[p]), hB[2 * p], hB[2 * p + 1]);
    }

    // ---- 32 residual layers: h += leaky(h @ W + b) ----
#pragma unroll 2
    for (int L = 0; L < N_LAYERS; L++) {
        const ulonglong2* w = reinterpret_cast<const ulonglong2*>(sWs + L * H * H);
        const ulonglong2* bb = reinterpret_cast<const ulonglong2*>(sBs + L * H);
        u64 aA[8], aB[8];
#pragma unroll
        for (int q = 0; q < 4; q++) {
            ulonglong2 t = bb[q];
            aA[2 * q] = t.x; aA[2 * q + 1] = t.y;
            aB[2 * q] = t.x; aB[2 * q + 1] = t.y;
        }
#pragma unroll
        for (int k = 0; k < H; k++) {
            const u64 vA = pack2(hA[k], hA[k]);
            const u64 vB = pack2(hB[k], hB[k]);
#pragma unroll
            for (int q = 0; q < 4; q++) {
                ulonglong2 wv = w[k * 4 + q];
                aA[2 * q]     = fma2(vA, wv.x, aA[2 * q]);
                aA[2 * q + 1] = fma2(vA, wv.y, aA[2 * q + 1]);
                aB[2 * q]     = fma2(vB, wv.x, aB[2 * q]);
                aB[2 * q + 1] = fma2(vB, wv.y, aB[2 * q + 1]);
            }
        }
        // fused residual+leaky: h' = h + 0.6t + 0.4|t|  (2 fma2 per u64, no FADD/mul2)
#pragma unroll
        for (int p = 0; p < 8; p++) {
            u64 hpA = pack2(hA[2 * p], hA[2 * p + 1]);
            unpack2(resleaky2(aA[p], hpA), hA[2 * p], hA[2 * p + 1]);
            u64 hpB = pack2(hB[2 * p], hB[2 * p + 1]);
            unpack2(resleaky2(aB[p], hpB), hB[2 * p], hB[2 * p + 1]);
        }
    }

    // ---- Final: out = h @ Wf + bf ----
    float oA = sBf, oB = sBf;
#pragma unroll
    for (int j = 0; j < H; j++) {
        oA = fmaf(hA[j], sWf[j], oA);
        oB = fmaf(hB[j], sWf[j], oB);
    }
    if (rowA < B) out[rowA] = oA;
    if (rowB < B) out[rowB] = oB;
}

extern "C" void kernel_launch(void* const* d_in, const int* in_sizes, int n_in,
                              void* d_out, int out_size)
{
    const float* z  = (const float*)d_in[0];
    const float* c  = (const float*)d_in[1];
    const float* W1 = (const float*)d_in[2];
    const float* b1 = (const float*)d_in[3];
    const float* Ws = (const float*)d_in[4];
    const float* bs = (const float*)d_in[5];
    const float* Wf = (const float*)d_in[6];
    const float* bf = (const float*)d_in[7];

    const int B = in_sizes[0] / 2;   // z is (B, 2)
    const int rows_per_block = THREADS * ROWS;
    const int blocks = (B + rows_per_block - 1) / rows_per_block;

    fractal_mlp_kernel<<<blocks, THREADS>>>(z, c, W1, b1, Ws, bs, Wf, bf,
                                            (float*)d_out, B);
}